// round 14
// baseline (speedup 1.0000x reference)
#include <cuda_runtime.h>

#define BB      4096
#define DD      8192
#define KK      5
#define GS      40
#define CKLEN   17
#define CKPAD   20
#define NTHR    256
#define TILE    2048                    // outputs per block
#define TILES_PER_ROW (DD / TILE)       // 4

// batch-global max of |g|/GS, produced by maxit_kernel
__device__ int g_maxit;

// ---------------------------------------------------------------------------
// Kernel A: tiny reduction, 1 block. max_it = max_b |g[b]| / GS
// ---------------------------------------------------------------------------
__global__ void __launch_bounds__(NTHR)
maxit_kernel(const int* __restrict__ g)
{
    __shared__ int s[NTHR / 32];
    const int t = threadIdx.x;
    const int4* g4 = reinterpret_cast<const int4*>(g);
    int m = 0;
    #pragma unroll
    for (int q = 0; q < 4; q++) {
        int4 v = __ldg(g4 + t + q * NTHR);
        int a0 = v.x < 0 ? -v.x : v.x;
        int a1 = v.y < 0 ? -v.y : v.y;
        int a2 = v.z < 0 ? -v.z : v.z;
        int a3 = v.w < 0 ? -v.w : v.w;
        m = max(m, max(max(a0, a1), max(a2, a3)));
    }
    m /= GS;
    #pragma unroll
    for (int o = 16; o > 0; o >>= 1)
        m = max(m, __shfl_xor_sync(0xffffffffu, m, o));
    if ((t & 31) == 0) s[t >> 5] = m;
    __syncthreads();
    if (t == 0) {
        #pragma unroll
        for (int w = 1; w < NTHR / 32; w++) m = max(m, s[w]);
        g_maxit = m;
    }
}

// ---------------------------------------------------------------------------
// Kernel B: fused compose + 17-tap circular correlation.
// Latency choreography:
//   (1) w0 window loads issue FIRST (independent of producer)
//   (2) warp 0 pre-loads g[b] + all 15 table taps (also independent of it)
//   (3) griddepsync -> warp-0 compose is pure ALU -> smem -> ONE barrier
//       (warps cross the barrier with their w0 loads already in flight)
//   (4) taps from smem, w1 loads, two FMA rounds, streaming stores
// ---------------------------------------------------------------------------
__global__ void __launch_bounds__(NTHR, 5)
conv_main(const float* __restrict__ x,
          const int*   __restrict__ g,
          const float* __restrict__ kernels,
          float*       __restrict__ out)
{
    __shared__ float s_k[CKPAD];

    const int bid  = blockIdx.x;
    const int b    = bid >> 2;              // TILES_PER_ROW = 4
    const int tile = bid & 3;
    const int lane = threadIdx.x & 31;
    const int warp = threadIdx.x >> 5;

    const float* __restrict__ xr = x + (size_t)b * DD;
    float* __restrict__ orow     = out + (size_t)b * DD;

    const int base4 = tile * (TILE / 4) + warp * 64 + lane;  // float4 index
    const int d0 = base4 * 4;
    const int d1 = d0 + 128;

    // ---- (1) round-0 window loads: in flight before any sync ----
    float w0[20];
    #pragma unroll
    for (int q = 0; q < 5; q++) {
        const int idx = (d0 - 8 + 4 * q) & (DD - 1);
        float4 v = __ldg(reinterpret_cast<const float4*>(xr + idx));
        w0[4*q+0] = v.x; w0[4*q+1] = v.y; w0[4*q+2] = v.z; w0[4*q+3] = v.w;
    }

    // ---- (2) warp 0: pre-load row params + table taps (no producer dep) ----
    int it = 0, max_it_dummy;
    float idk[KK], maxk[KK], fink[KK];
    if (warp == 0) {
        const int gv  = __ldg(g + b);
        const int sgn = (gv > 0) - (gv < 0);
        const int av  = gv < 0 ? -gv : gv;
        it = av / GS;
        const int rem = av - it * GS;
        const int midx = sgn * 40 + 40;
        const int fidx = rem * sgn + 40;
        #pragma unroll
        for (int j = 0; j < KK; j++) {
            idk[j]  = __ldg(kernels + 40   * KK + j);
            maxk[j] = __ldg(kernels + midx * KK + j);
            fink[j] = __ldg(kernels + fidx * KK + j);
        }
    }

#if __CUDA_ARCH__ >= 900
    cudaGridDependencySynchronize();   // only g_maxit depends on kernel A
#endif

    // ---- (3) warp 0: pure-ALU compose (lane p = tap p), verified in R11 ----
    if (warp == 0) {
        const int max_it = g_maxit;

        float c = (lane == 8) ? 1.f : 0.f;

        #pragma unroll
        for (int stage = 0; stage < 4; stage++) {
            float k0, k1, k2, k3, k4;
            bool skip = false;
            if (stage == 3) {
                k0=fink[0]; k1=fink[1]; k2=fink[2]; k3=fink[3]; k4=fink[4];
            } else if (stage < it) {
                k0=maxk[0]; k1=maxk[1]; k2=maxk[2]; k3=maxk[3]; k4=maxk[4];
            } else if (stage < max_it) {
                k0=idk[0];  k1=idk[1];  k2=idk[2];  k3=idk[3];  k4=idk[4];
            } else {
                skip = true;           // true delta -> identity
                k0=k1=k2=k3=k4=0.f;
            }
            if (!skip) {
                // new_c[p] = sum_j kk[j] * c[p - j + 2]
                float cd2 = __shfl_down_sync(0xffffffffu, c, 2);
                float cd1 = __shfl_down_sync(0xffffffffu, c, 1);
                float cu1 = __shfl_up_sync  (0xffffffffu, c, 1);
                float cu2 = __shfl_up_sync  (0xffffffffu, c, 2);
                float nc;
                nc = k0 * cd2;
                nc = fmaf(k1, cd1, nc);
                nc = fmaf(k2, c,   nc);
                nc = fmaf(k3, cu1, nc);
                nc = fmaf(k4, cu2, nc);
                c = nc;
            }
        }

        if (lane < CKPAD) s_k[lane] = (lane < CKLEN) ? c : 0.f;
    }
    __syncthreads();

    // ---- (4) taps from smem (broadcast, conflict-free) ----
    float k[CKLEN];
    {
        const float4* sk = reinterpret_cast<const float4*>(s_k);
        float4 k0 = sk[0], k1 = sk[1], k2 = sk[2], k3 = sk[3], k4 = sk[4];
        k[0]=k0.x;  k[1]=k0.y;  k[2]=k0.z;  k[3]=k0.w;
        k[4]=k1.x;  k[5]=k1.y;  k[6]=k1.z;  k[7]=k1.w;
        k[8]=k2.x;  k[9]=k2.y;  k[10]=k2.z; k[11]=k2.w;
        k[12]=k3.x; k[13]=k3.y; k[14]=k3.z; k[15]=k3.w;
        k[16]=k4.x;
    }

    // ---- round-1 window loads ----
    float w1[20];
    #pragma unroll
    for (int q = 0; q < 5; q++) {
        const int idx = (d1 - 8 + 4 * q) & (DD - 1);
        float4 v = __ldg(reinterpret_cast<const float4*>(xr + idx));
        w1[4*q+0] = v.x; w1[4*q+1] = v.y; w1[4*q+2] = v.z; w1[4*q+3] = v.w;
    }

    // ---- round 0 ----
    {
        float a0 = 0.f, a1 = 0.f, a2 = 0.f, a3 = 0.f;
        #pragma unroll
        for (int p = 0; p < CKLEN; p++) {
            a0 = fmaf(k[p], w0[p + 0], a0);
            a1 = fmaf(k[p], w0[p + 1], a1);
            a2 = fmaf(k[p], w0[p + 2], a2);
            a3 = fmaf(k[p], w0[p + 3], a3);
        }
        __stcs(reinterpret_cast<float4*>(orow + d0), make_float4(a0, a1, a2, a3));
    }

    // ---- round 1 ----
    {
        float a0 = 0.f, a1 = 0.f, a2 = 0.f, a3 = 0.f;
        #pragma unroll
        for (int p = 0; p < CKLEN; p++) {
            a0 = fmaf(k[p], w1[p + 0], a0);
            a1 = fmaf(k[p], w1[p + 1], a1);
            a2 = fmaf(k[p], w1[p + 2], a2);
            a3 = fmaf(k[p], w1[p + 3], a3);
        }
        __stcs(reinterpret_cast<float4*>(orow + d1), make_float4(a0, a1, a2, a3));
    }
}

// ---------------------------------------------------------------------------
// Launch: tiny max reduce, then fused conv with PDL.
// ---------------------------------------------------------------------------
extern "C" void kernel_launch(void* const* d_in, const int* in_sizes, int n_in,
                              void* d_out, int out_size)
{
    const float* x       = (const float*)d_in[0];   // [4096, 8192] f32
    const int*   g       = (const int*)  d_in[1];   // [4096] i32
    const float* kernels = (const float*)d_in[2];   // [81, 5] f32
    float*       out     = (float*)d_out;           // [4096, 1, 8192] f32

    maxit_kernel<<<1, NTHR>>>(g);

    cudaLaunchConfig_t cfg = {};
    cfg.gridDim  = dim3(BB * TILES_PER_ROW, 1, 1);
    cfg.blockDim = dim3(NTHR, 1, 1);
    cfg.dynamicSmemBytes = 0;
    cfg.stream = 0;   // legacy default stream (the one the harness captures)
    cudaLaunchAttribute attrs[1];
    attrs[0].id = cudaLaunchAttributeProgrammaticStreamSerialization;
    attrs[0].val.programmaticStreamSerializationAllowed = 1;
    cfg.attrs = attrs;
    cfg.numAttrs = 1;
    cudaLaunchKernelEx(&cfg, conv_main, x, g, kernels, out);
}

// round 15
// speedup vs baseline: 1.0180x; 1.0180x over previous
#include <cuda_runtime.h>

#define BB      4096
#define DD      8192
#define KK      5
#define GS      40
#define CKLEN   17
#define CKPAD   20
#define NTHR    256
#define TILE    2048                    // outputs per block
#define TILES_PER_ROW (DD / TILE)       // 4
#define ROW4    (DD / 4)                // 2048 float4s per row
#define ROW4M   (ROW4 - 1)

#define CNTHR   256                     // compose block size
#define CBLK    (BB / CNTHR)            // 16 compose blocks

// Composed per-row 17-tap kernels, padded to 20 floats (327 KB, L2-resident)
__device__ float g_ck[BB * CKPAD];

// ---------------------------------------------------------------------------
// Kernel 1 (R12 verbatim): compose each row's 17-tap kernel.
// ---------------------------------------------------------------------------
__global__ void __launch_bounds__(CNTHR)
compose_kernel(const int* __restrict__ g, const float* __restrict__ kernels)
{
    __shared__ int s_red[CNTHR / 32];
    const int t = threadIdx.x;
    const int b = blockIdx.x * CNTHR + t;

    const int4* g4 = reinterpret_cast<const int4*>(g);
    int m = 0;
    #pragma unroll
    for (int q = 0; q < 4; q++) {
        int4 v = __ldg(g4 + t + q * CNTHR);
        int a0 = v.x < 0 ? -v.x : v.x;
        int a1 = v.y < 0 ? -v.y : v.y;
        int a2 = v.z < 0 ? -v.z : v.z;
        int a3 = v.w < 0 ? -v.w : v.w;
        m = max(m, max(max(a0, a1), max(a2, a3)));
    }
    m /= GS;
    #pragma unroll
    for (int o = 16; o > 0; o >>= 1)
        m = max(m, __shfl_xor_sync(0xffffffffu, m, o));
    if ((t & 31) == 0) s_red[t >> 5] = m;
    __syncthreads();
    int max_it = s_red[0];
    #pragma unroll
    for (int w = 1; w < CNTHR / 32; w++) max_it = max(max_it, s_red[w]);

    const int gv  = g[b];
    const int sgn = (gv > 0) - (gv < 0);
    const int av  = gv < 0 ? -gv : gv;
    const int it  = av / GS;
    const int rem = av - it * GS;

    const int midx = sgn * 40 + 40;
    const int fidx = rem * sgn + 40;

    float idk[KK], maxk[KK], fink[KK];
    #pragma unroll
    for (int j = 0; j < KK; j++) {
        idk[j]  = __ldg(kernels + 40   * KK + j);
        maxk[j] = __ldg(kernels + midx * KK + j);
        fink[j] = __ldg(kernels + fidx * KK + j);
    }

    float c[CKLEN];
    #pragma unroll
    for (int p = 0; p < CKLEN; p++) c[p] = 0.f;
    c[8] = 1.f;

    #pragma unroll
    for (int stage = 0; stage < 4; stage++) {
        float kk[KK];
        bool skip = false;
        if (stage == 3) {
            #pragma unroll
            for (int j = 0; j < KK; j++) kk[j] = fink[j];
        } else if (stage < it) {
            #pragma unroll
            for (int j = 0; j < KK; j++) kk[j] = maxk[j];
        } else if (stage < max_it) {
            #pragma unroll
            for (int j = 0; j < KK; j++) kk[j] = idk[j];
        } else {
            skip = true;
        }
        if (!skip) {
            float nc[CKLEN];
            #pragma unroll
            for (int p = 0; p < CKLEN; p++) {
                float a = 0.f;
                #pragma unroll
                for (int j = 0; j < KK; j++) {
                    int q = p - j + 2;
                    if (q >= 0 && q < CKLEN) a = fmaf(kk[j], c[q], a);
                }
                nc[p] = a;
            }
            #pragma unroll
            for (int p = 0; p < CKLEN; p++) c[p] = nc[p];
        }
    }

    float4* dst = reinterpret_cast<float4*>(g_ck + b * CKPAD);
    dst[0] = make_float4(c[0],  c[1],  c[2],  c[3]);
    dst[1] = make_float4(c[4],  c[5],  c[6],  c[7]);
    dst[2] = make_float4(c[8],  c[9],  c[10], c[11]);
    dst[3] = make_float4(c[12], c[13], c[14], c[15]);
    dst[4] = make_float4(c[16], 0.f,   0.f,   0.f);
}

// ---------------------------------------------------------------------------
// Shuffle helpers (per-component, full mask)
// ---------------------------------------------------------------------------
__device__ __forceinline__ float4 shfl_up4(float4 v, int n) {
    float4 r;
    r.x = __shfl_up_sync(0xffffffffu, v.x, n);
    r.y = __shfl_up_sync(0xffffffffu, v.y, n);
    r.z = __shfl_up_sync(0xffffffffu, v.z, n);
    r.w = __shfl_up_sync(0xffffffffu, v.w, n);
    return r;
}
__device__ __forceinline__ float4 shfl_dn4(float4 v, int n) {
    float4 r;
    r.x = __shfl_down_sync(0xffffffffu, v.x, n);
    r.y = __shfl_down_sync(0xffffffffu, v.y, n);
    r.z = __shfl_down_sync(0xffffffffu, v.z, n);
    r.w = __shfl_down_sync(0xffffffffu, v.w, n);
    return r;
}

// edge loads: only lanes 0,1,30,31 touch memory (dual-role registers)
__device__ __forceinline__ void edge_loads(const float4* __restrict__ xr4,
                                           int f, int lane,
                                           float4& ea, float4& eb)
{
    if (lane < 2)        ea = __ldg(xr4 + ((f - 2) & ROW4M));   // L2 fix
    else if (lane >= 30) ea = __ldg(xr4 + ((f + 2) & ROW4M));   // R2 fix
    if (lane == 0)       eb = __ldg(xr4 + ((f - 1) & ROW4M));   // L1 fix
    else if (lane == 31) eb = __ldg(xr4 + ((f + 1) & ROW4M));   // R1 fix
}

// one round: own float4 + shuffled halo -> 4 outputs
// out[d+i] = sum_p k[p] * x[d-8+ (i+p)], chunks streamed L2,L1,own,R1,R2
__device__ __forceinline__ float4 conv_round(float4 own, float4 ea, float4 eb,
                                             const float* k, int lane)
{
    float a0 = 0.f, a1 = 0.f, a2 = 0.f, a3 = 0.f;

#define APPLY_ELEM(j, wv) do {                                   \
        if ((j) >= 0 && (j) <= 16) a0 = fmaf(k[(j)],     (wv), a0); \
        if ((j) >= 1 && (j) <= 17) a1 = fmaf(k[(j) - 1], (wv), a1); \
        if ((j) >= 2 && (j) <= 18) a2 = fmaf(k[(j) - 2], (wv), a2); \
        if ((j) >= 3 && (j) <= 19) a3 = fmaf(k[(j) - 3], (wv), a3); \
    } while (0)
#define APPLY_CHUNK(m, c4) do {                                  \
        APPLY_ELEM(4 * (m) + 0, (c4).x);                         \
        APPLY_ELEM(4 * (m) + 1, (c4).y);                         \
        APPLY_ELEM(4 * (m) + 2, (c4).z);                         \
        APPLY_ELEM(4 * (m) + 3, (c4).w);                         \
    } while (0)

    float4 c;
    c = shfl_up4(own, 2); if (lane < 2)   c = ea;   // w[0..3]   = x4[f-2]
    APPLY_CHUNK(0, c);
    c = shfl_up4(own, 1); if (lane == 0)  c = eb;   // w[4..7]   = x4[f-1]
    APPLY_CHUNK(1, c);
    APPLY_CHUNK(2, own);                            // w[8..11]  = x4[f]
    c = shfl_dn4(own, 1); if (lane == 31) c = eb;   // w[12..15] = x4[f+1]
    APPLY_CHUNK(3, c);
    c = shfl_dn4(own, 2); if (lane >= 30) c = ea;   // w[16..19] = x4[f+2]
    APPLY_CHUNK(4, c);

#undef APPLY_CHUNK
#undef APPLY_ELEM
    return make_float4(a0, a1, a2, a3);
}

// ---------------------------------------------------------------------------
// Kernel 2: 17-tap circular correlation, shuffle-assembled halos.
// Per thread per round: 1 own LDG.128 (+tiny edge loads on 4 lanes),
// 16 SHFL, 68 FMA, 1 STG.128. L1 wavefronts/block ~230 vs ~424 before.
// ---------------------------------------------------------------------------
__global__ void __launch_bounds__(NTHR, 6)
conv_main(const float* __restrict__ x, float* __restrict__ out)
{
    const int bid  = blockIdx.x;
    const int b    = bid >> 2;              // TILES_PER_ROW = 4
    const int tile = bid & 3;
    const int lane = threadIdx.x & 31;
    const int warp = threadIdx.x >> 5;

    const float4* __restrict__ xr4 =
        reinterpret_cast<const float4*>(x + (size_t)b * DD);
    float4* __restrict__ or4 =
        reinterpret_cast<float4*>(out + (size_t)b * DD);

    const int f0 = tile * (TILE / 4) + warp * 64 + lane;  // own float4, round 0
    const int f1 = f0 + 32;

    // ---- pre-sync: all round-0 loads + round-1 own, in flight over compose ----
    float4 own0 = __ldg(xr4 + f0);
    float4 own1 = __ldg(xr4 + f1);
    float4 ea0, eb0;
    edge_loads(xr4, f0, lane, ea0, eb0);

#if __CUDA_ARCH__ >= 900
    cudaGridDependencySynchronize();   // wait for compose_kernel (g_ck)
#endif

    // row taps: 5 vector loads (uniform across block, L2-resident)
    float k[CKLEN];
    {
        const float4* ckp = reinterpret_cast<const float4*>(g_ck + b * CKPAD);
        float4 k0 = __ldg(ckp + 0);
        float4 k1 = __ldg(ckp + 1);
        float4 k2 = __ldg(ckp + 2);
        float4 k3 = __ldg(ckp + 3);
        float4 k4 = __ldg(ckp + 4);
        k[0]=k0.x;  k[1]=k0.y;  k[2]=k0.z;  k[3]=k0.w;
        k[4]=k1.x;  k[5]=k1.y;  k[6]=k1.z;  k[7]=k1.w;
        k[8]=k2.x;  k[9]=k2.y;  k[10]=k2.z; k[11]=k2.w;
        k[12]=k3.x; k[13]=k3.y; k[14]=k3.z; k[15]=k3.w;
        k[16]=k4.x;
    }

    // ---- round 0 ----
    float4 o0 = conv_round(own0, ea0, eb0, k, lane);
    __stcs(or4 + f0, o0);

    // ---- round 1 (edge loads issued after round-0 regs die) ----
    float4 ea1, eb1;
    edge_loads(xr4, f1, lane, ea1, eb1);
    float4 o1 = conv_round(own1, ea1, eb1, k, lane);
    __stcs(or4 + f1, o1);
}

// ---------------------------------------------------------------------------
// Launch (R12 structure): compose, then conv with PDL.
// ---------------------------------------------------------------------------
extern "C" void kernel_launch(void* const* d_in, const int* in_sizes, int n_in,
                              void* d_out, int out_size)
{
    const float* x       = (const float*)d_in[0];   // [4096, 8192] f32
    const int*   g       = (const int*)  d_in[1];   // [4096] i32
    const float* kernels = (const float*)d_in[2];   // [81, 5] f32
    float*       out     = (float*)d_out;           // [4096, 1, 8192] f32

    compose_kernel<<<CBLK, CNTHR>>>(g, kernels);

    cudaLaunchConfig_t cfg = {};
    cfg.gridDim  = dim3(BB * TILES_PER_ROW, 1, 1);
    cfg.blockDim = dim3(NTHR, 1, 1);
    cfg.dynamicSmemBytes = 0;
    cfg.stream = 0;   // legacy default stream (the one the harness captures)
    cudaLaunchAttribute attrs[1];
    attrs[0].id = cudaLaunchAttributeProgrammaticStreamSerialization;
    attrs[0].val.programmaticStreamSerializationAllowed = 1;
    cfg.attrs = attrs;
    cfg.numAttrs = 1;
    cudaLaunchKernelEx(&cfg, conv_main, x, out);
}

// round 16
// speedup vs baseline: 1.2323x; 1.2106x over previous
#include <cuda_runtime.h>

#define BB      4096
#define DD      8192
#define KK      5
#define GS      40
#define CKLEN   17
#define CKPAD   20
#define NTHR    256
#define TILE    2048                    // outputs per block
#define TILES_PER_ROW (DD / TILE)       // 4

#define TABN    (81 * KK)               // 405 floats, whole kernels table

#define CNTHR   128                     // compose block size
#define CBLK    (BB / CNTHR)            // 32 compose blocks

// batch-global max of |g|/GS
__device__ int g_maxit;
// Composed per-row 17-tap kernels, padded to 20 floats (327 KB, L2-resident)
__device__ float g_ck[BB * CKPAD];

// ---------------------------------------------------------------------------
// Kernel A: tiny reduction, 1 block. max_it = max_b |g[b]| / GS
// ---------------------------------------------------------------------------
__global__ void __launch_bounds__(NTHR)
maxit_kernel(const int* __restrict__ g)
{
    __shared__ int s[NTHR / 32];
    const int t = threadIdx.x;
    const int4* g4 = reinterpret_cast<const int4*>(g);
    int m = 0;
    #pragma unroll
    for (int q = 0; q < 4; q++) {
        int4 v = __ldg(g4 + t + q * NTHR);
        int a0 = v.x < 0 ? -v.x : v.x;
        int a1 = v.y < 0 ? -v.y : v.y;
        int a2 = v.z < 0 ? -v.z : v.z;
        int a3 = v.w < 0 ? -v.w : v.w;
        m = max(m, max(max(a0, a1), max(a2, a3)));
    }
    m /= GS;
    #pragma unroll
    for (int o = 16; o > 0; o >>= 1)
        m = max(m, __shfl_xor_sync(0xffffffffu, m, o));
    if ((t & 31) == 0) s[t >> 5] = m;
    __syncthreads();
    if (t == 0) {
        #pragma unroll
        for (int w = 1; w < NTHR / 32; w++) m = max(m, s[w]);
        g_maxit = m;
    }
}

// ---------------------------------------------------------------------------
// Kernel B: compose each row's 17-tap kernel (one row per thread).
// All DRAM traffic (g[b], whole kernels table -> smem) issues BEFORE the
// PDL sync, overlapping maxit_kernel. Post-sync it is smem + ALU only.
// ---------------------------------------------------------------------------
__global__ void __launch_bounds__(CNTHR)
compose2(const int* __restrict__ g, const float* __restrict__ kernels)
{
    __shared__ float s_tab[TABN];
    const int t = threadIdx.x;
    const int b = blockIdx.x * CNTHR + t;

    // stage full table (coalesced, independent of the producer)
    #pragma unroll
    for (int i = t; i < TABN; i += CNTHR) s_tab[i] = __ldg(kernels + i);

    // row params (independent of the producer)
    const int gv  = __ldg(g + b);
    const int sgn = (gv > 0) - (gv < 0);
    const int av  = gv < 0 ? -gv : gv;
    const int it  = av / GS;
    const int rem = av - it * GS;
    const int midx = sgn * 40 + 40;
    const int fidx = rem * sgn + 40;

#if __CUDA_ARCH__ >= 900
    cudaGridDependencySynchronize();   // wait only for g_maxit
#endif
    const int max_it = g_maxit;
    __syncthreads();                   // table staged

    float idk[KK], maxk[KK], fink[KK];
    #pragma unroll
    for (int j = 0; j < KK; j++) {
        idk[j]  = s_tab[40   * KK + j];
        maxk[j] = s_tab[midx * KK + j];
        fink[j] = s_tab[fidx * KK + j];
    }

    float c[CKLEN];
    #pragma unroll
    for (int p = 0; p < CKLEN; p++) c[p] = 0.f;
    c[8] = 1.f;

    #pragma unroll
    for (int stage = 0; stage < 4; stage++) {
        float kk[KK];
        bool skip = false;
        if (stage == 3) {
            #pragma unroll
            for (int j = 0; j < KK; j++) kk[j] = fink[j];
        } else if (stage < it) {
            #pragma unroll
            for (int j = 0; j < KK; j++) kk[j] = maxk[j];
        } else if (stage < max_it) {
            #pragma unroll
            for (int j = 0; j < KK; j++) kk[j] = idk[j];
        } else {
            skip = true;               // true delta -> identity
        }
        if (!skip) {
            float nc[CKLEN];
            #pragma unroll
            for (int p = 0; p < CKLEN; p++) {
                float a = 0.f;
                #pragma unroll
                for (int j = 0; j < KK; j++) {
                    int q = p - j + 2;
                    if (q >= 0 && q < CKLEN) a = fmaf(kk[j], c[q], a);
                }
                nc[p] = a;
            }
            #pragma unroll
            for (int p = 0; p < CKLEN; p++) c[p] = nc[p];
        }
    }

    float4* dst = reinterpret_cast<float4*>(g_ck + b * CKPAD);
    dst[0] = make_float4(c[0],  c[1],  c[2],  c[3]);
    dst[1] = make_float4(c[4],  c[5],  c[6],  c[7]);
    dst[2] = make_float4(c[8],  c[9],  c[10], c[11]);
    dst[3] = make_float4(c[12], c[13], c[14], c[15]);
    dst[4] = make_float4(c[16], 0.f,   0.f,   0.f);
}

// ---------------------------------------------------------------------------
// Kernel C (R12 body, UNCHANGED — proven 44.8us): 17-tap circular
// correlation, lane-interleaved float4s, all 10 window loads before the
// PDL sync so they overlap compose2.
// ---------------------------------------------------------------------------
__global__ void __launch_bounds__(NTHR)
conv_main(const float* __restrict__ x, float* __restrict__ out)
{
    const int bid  = blockIdx.x;
    const int b    = bid >> 2;              // TILES_PER_ROW = 4
    const int tile = bid & 3;
    const int lane = threadIdx.x & 31;
    const int warp = threadIdx.x >> 5;

    const float* __restrict__ xr = x + (size_t)b * DD;
    float* __restrict__ orow     = out + (size_t)b * DD;

    const int base4 = tile * (TILE / 4) + warp * 64 + lane;  // float4 index
    const int d0 = base4 * 4;
    const int d1 = d0 + 128;

    // ---- issue all 10 window loads (x has no dependency on compose) ----
    float w0[20], w1[20];
    #pragma unroll
    for (int q = 0; q < 5; q++) {
        const int idx = (d0 - 8 + 4 * q) & (DD - 1);
        float4 v = __ldg(reinterpret_cast<const float4*>(xr + idx));
        w0[4*q+0] = v.x; w0[4*q+1] = v.y; w0[4*q+2] = v.z; w0[4*q+3] = v.w;
    }
    #pragma unroll
    for (int q = 0; q < 5; q++) {
        const int idx = (d1 - 8 + 4 * q) & (DD - 1);
        float4 v = __ldg(reinterpret_cast<const float4*>(xr + idx));
        w1[4*q+0] = v.x; w1[4*q+1] = v.y; w1[4*q+2] = v.z; w1[4*q+3] = v.w;
    }

#if __CUDA_ARCH__ >= 900
    cudaGridDependencySynchronize();   // wait for compose2 (g_ck)
#endif

    // row taps: 5 vector loads (uniform across block, L2-resident)
    float k[CKLEN];
    {
        const float4* ckp = reinterpret_cast<const float4*>(g_ck + b * CKPAD);
        float4 k0 = __ldg(ckp + 0);
        float4 k1 = __ldg(ckp + 1);
        float4 k2 = __ldg(ckp + 2);
        float4 k3 = __ldg(ckp + 3);
        float4 k4 = __ldg(ckp + 4);
        k[0]=k0.x;  k[1]=k0.y;  k[2]=k0.z;  k[3]=k0.w;
        k[4]=k1.x;  k[5]=k1.y;  k[6]=k1.z;  k[7]=k1.w;
        k[8]=k2.x;  k[9]=k2.y;  k[10]=k2.z; k[11]=k2.w;
        k[12]=k3.x; k[13]=k3.y; k[14]=k3.z; k[15]=k3.w;
        k[16]=k4.x;
    }

    // ---- round 0 ----
    {
        float a0 = 0.f, a1 = 0.f, a2 = 0.f, a3 = 0.f;
        #pragma unroll
        for (int p = 0; p < CKLEN; p++) {
            a0 = fmaf(k[p], w0[p + 0], a0);
            a1 = fmaf(k[p], w0[p + 1], a1);
            a2 = fmaf(k[p], w0[p + 2], a2);
            a3 = fmaf(k[p], w0[p + 3], a3);
        }
        __stcs(reinterpret_cast<float4*>(orow + d0), make_float4(a0, a1, a2, a3));
    }

    // ---- round 1 ----
    {
        float a0 = 0.f, a1 = 0.f, a2 = 0.f, a3 = 0.f;
        #pragma unroll
        for (int p = 0; p < CKLEN; p++) {
            a0 = fmaf(k[p], w1[p + 0], a0);
            a1 = fmaf(k[p], w1[p + 1], a1);
            a2 = fmaf(k[p], w1[p + 2], a2);
            a3 = fmaf(k[p], w1[p + 3], a3);
        }
        __stcs(reinterpret_cast<float4*>(orow + d1), make_float4(a0, a1, a2, a3));
    }
}

// ---------------------------------------------------------------------------
// Launch: maxit -> compose2 (PDL) -> conv (PDL). compose2's DRAM prologue
// overlaps maxit; conv's x-load prologue overlaps compose2.
// ---------------------------------------------------------------------------
extern "C" void kernel_launch(void* const* d_in, const int* in_sizes, int n_in,
                              void* d_out, int out_size)
{
    const float* x       = (const float*)d_in[0];   // [4096, 8192] f32
    const int*   g       = (const int*)  d_in[1];   // [4096] i32
    const float* kernels = (const float*)d_in[2];   // [81, 5] f32
    float*       out     = (float*)d_out;           // [4096, 1, 8192] f32

    maxit_kernel<<<1, NTHR>>>(g);

    cudaLaunchAttribute attrs[1];
    attrs[0].id = cudaLaunchAttributeProgrammaticStreamSerialization;
    attrs[0].val.programmaticStreamSerializationAllowed = 1;

    {
        cudaLaunchConfig_t cfg = {};
        cfg.gridDim  = dim3(CBLK, 1, 1);
        cfg.blockDim = dim3(CNTHR, 1, 1);
        cfg.dynamicSmemBytes = 0;
        cfg.stream = 0;
        cfg.attrs = attrs;
        cfg.numAttrs = 1;
        cudaLaunchKernelEx(&cfg, compose2, g, kernels);
    }
    {
        cudaLaunchConfig_t cfg = {};
        cfg.gridDim  = dim3(BB * TILES_PER_ROW, 1, 1);
        cfg.blockDim = dim3(NTHR, 1, 1);
        cfg.dynamicSmemBytes = 0;
        cfg.stream = 0;
        cfg.attrs = attrs;
        cfg.numAttrs = 1;
        cudaLaunchKernelEx(&cfg, conv_main, x, out);
    }
}

// round 17
// speedup vs baseline: 1.2385x; 1.0050x over previous
#include <cuda_runtime.h>

#define BB      4096
#define DD      8192
#define KK      5
#define GS      40
#define CKLEN   17
#define CKPAD   20
#define NTHR    256
#define TILE    2048                    // outputs per block
#define TILES_PER_ROW (DD / TILE)       // 4

#define TABN    (81 * KK)               // 405 floats, whole kernels table

#define CNTHR   128                     // compose block size
#define CBLK    (BB / CNTHR)            // 32 compose blocks

// batch-global max of |g|/GS
__device__ int g_maxit;
// Composed per-row 17-tap kernels, padded to 20 floats (327 KB, L2-resident)
__device__ float g_ck[BB * CKPAD];

// ---------------------------------------------------------------------------
// Kernel A: tiny reduction, 1 block. max_it = max_b |g[b]| / GS
// ---------------------------------------------------------------------------
__global__ void __launch_bounds__(NTHR)
maxit_kernel(const int* __restrict__ g)
{
    __shared__ int s[NTHR / 32];
    const int t = threadIdx.x;
    const int4* g4 = reinterpret_cast<const int4*>(g);
    int m = 0;
    #pragma unroll
    for (int q = 0; q < 4; q++) {
        int4 v = __ldg(g4 + t + q * NTHR);
        int a0 = v.x < 0 ? -v.x : v.x;
        int a1 = v.y < 0 ? -v.y : v.y;
        int a2 = v.z < 0 ? -v.z : v.z;
        int a3 = v.w < 0 ? -v.w : v.w;
        m = max(m, max(max(a0, a1), max(a2, a3)));
    }
    m /= GS;
    #pragma unroll
    for (int o = 16; o > 0; o >>= 1)
        m = max(m, __shfl_xor_sync(0xffffffffu, m, o));
    if ((t & 31) == 0) s[t >> 5] = m;
    __syncthreads();
    if (t == 0) {
        #pragma unroll
        for (int w = 1; w < NTHR / 32; w++) m = max(m, s[w]);
        g_maxit = m;
    }
}

// ---------------------------------------------------------------------------
// Kernel B: compose each row's 17-tap kernel (one row per thread).
// All DRAM traffic (g[b], whole kernels table -> smem) issues BEFORE the
// PDL sync, overlapping maxit_kernel. Post-sync it is smem + ALU only.
// ---------------------------------------------------------------------------
__global__ void __launch_bounds__(CNTHR)
compose2(const int* __restrict__ g, const float* __restrict__ kernels)
{
    __shared__ float s_tab[TABN];
    const int t = threadIdx.x;
    const int b = blockIdx.x * CNTHR + t;

    // stage full table (coalesced, independent of the producer)
    #pragma unroll
    for (int i = t; i < TABN; i += CNTHR) s_tab[i] = __ldg(kernels + i);

    // row params (independent of the producer)
    const int gv  = __ldg(g + b);
    const int sgn = (gv > 0) - (gv < 0);
    const int av  = gv < 0 ? -gv : gv;
    const int it  = av / GS;
    const int rem = av - it * GS;
    const int midx = sgn * 40 + 40;
    const int fidx = rem * sgn + 40;

#if __CUDA_ARCH__ >= 900
    cudaGridDependencySynchronize();   // wait only for g_maxit
#endif
    const int max_it = g_maxit;
    __syncthreads();                   // table staged

    float idk[KK], maxk[KK], fink[KK];
    #pragma unroll
    for (int j = 0; j < KK; j++) {
        idk[j]  = s_tab[40   * KK + j];
        maxk[j] = s_tab[midx * KK + j];
        fink[j] = s_tab[fidx * KK + j];
    }

    float c[CKLEN];
    #pragma unroll
    for (int p = 0; p < CKLEN; p++) c[p] = 0.f;
    c[8] = 1.f;

    #pragma unroll
    for (int stage = 0; stage < 4; stage++) {
        float kk[KK];
        bool skip = false;
        if (stage == 3) {
            #pragma unroll
            for (int j = 0; j < KK; j++) kk[j] = fink[j];
        } else if (stage < it) {
            #pragma unroll
            for (int j = 0; j < KK; j++) kk[j] = maxk[j];
        } else if (stage < max_it) {
            #pragma unroll
            for (int j = 0; j < KK; j++) kk[j] = idk[j];
        } else {
            skip = true;               // true delta -> identity
        }
        if (!skip) {
            float nc[CKLEN];
            #pragma unroll
            for (int p = 0; p < CKLEN; p++) {
                float a = 0.f;
                #pragma unroll
                for (int j = 0; j < KK; j++) {
                    int q = p - j + 2;
                    if (q >= 0 && q < CKLEN) a = fmaf(kk[j], c[q], a);
                }
                nc[p] = a;
            }
            #pragma unroll
            for (int p = 0; p < CKLEN; p++) c[p] = nc[p];
        }
    }

    float4* dst = reinterpret_cast<float4*>(g_ck + b * CKPAD);
    dst[0] = make_float4(c[0],  c[1],  c[2],  c[3]);
    dst[1] = make_float4(c[4],  c[5],  c[6],  c[7]);
    dst[2] = make_float4(c[8],  c[9],  c[10], c[11]);
    dst[3] = make_float4(c[12], c[13], c[14], c[15]);
    dst[4] = make_float4(c[16], 0.f,   0.f,   0.f);
}

// ---------------------------------------------------------------------------
// Kernel C (R12 body, UNCHANGED — proven 44.8us): 17-tap circular
// correlation, lane-interleaved float4s, all 10 window loads before the
// PDL sync so they overlap compose2.
// ---------------------------------------------------------------------------
__global__ void __launch_bounds__(NTHR)
conv_main(const float* __restrict__ x, float* __restrict__ out)
{
    const int bid  = blockIdx.x;
    const int b    = bid >> 2;              // TILES_PER_ROW = 4
    const int tile = bid & 3;
    const int lane = threadIdx.x & 31;
    const int warp = threadIdx.x >> 5;

    const float* __restrict__ xr = x + (size_t)b * DD;
    float* __restrict__ orow     = out + (size_t)b * DD;

    const int base4 = tile * (TILE / 4) + warp * 64 + lane;  // float4 index
    const int d0 = base4 * 4;
    const int d1 = d0 + 128;

    // ---- issue all 10 window loads (x has no dependency on compose) ----
    float w0[20], w1[20];
    #pragma unroll
    for (int q = 0; q < 5; q++) {
        const int idx = (d0 - 8 + 4 * q) & (DD - 1);
        float4 v = __ldg(reinterpret_cast<const float4*>(xr + idx));
        w0[4*q+0] = v.x; w0[4*q+1] = v.y; w0[4*q+2] = v.z; w0[4*q+3] = v.w;
    }
    #pragma unroll
    for (int q = 0; q < 5; q++) {
        const int idx = (d1 - 8 + 4 * q) & (DD - 1);
        float4 v = __ldg(reinterpret_cast<const float4*>(xr + idx));
        w1[4*q+0] = v.x; w1[4*q+1] = v.y; w1[4*q+2] = v.z; w1[4*q+3] = v.w;
    }

#if __CUDA_ARCH__ >= 900
    cudaGridDependencySynchronize();   // wait for compose2 (g_ck)
#endif

    // row taps: 5 vector loads (uniform across block, L2-resident)
    float k[CKLEN];
    {
        const float4* ckp = reinterpret_cast<const float4*>(g_ck + b * CKPAD);
        float4 k0 = __ldg(ckp + 0);
        float4 k1 = __ldg(ckp + 1);
        float4 k2 = __ldg(ckp + 2);
        float4 k3 = __ldg(ckp + 3);
        float4 k4 = __ldg(ckp + 4);
        k[0]=k0.x;  k[1]=k0.y;  k[2]=k0.z;  k[3]=k0.w;
        k[4]=k1.x;  k[5]=k1.y;  k[6]=k1.z;  k[7]=k1.w;
        k[8]=k2.x;  k[9]=k2.y;  k[10]=k2.z; k[11]=k2.w;
        k[12]=k3.x; k[13]=k3.y; k[14]=k3.z; k[15]=k3.w;
        k[16]=k4.x;
    }

    // ---- round 0 ----
    {
        float a0 = 0.f, a1 = 0.f, a2 = 0.f, a3 = 0.f;
        #pragma unroll
        for (int p = 0; p < CKLEN; p++) {
            a0 = fmaf(k[p], w0[p + 0], a0);
            a1 = fmaf(k[p], w0[p + 1], a1);
            a2 = fmaf(k[p], w0[p + 2], a2);
            a3 = fmaf(k[p], w0[p + 3], a3);
        }
        __stcs(reinterpret_cast<float4*>(orow + d0), make_float4(a0, a1, a2, a3));
    }

    // ---- round 1 ----
    {
        float a0 = 0.f, a1 = 0.f, a2 = 0.f, a3 = 0.f;
        #pragma unroll
        for (int p = 0; p < CKLEN; p++) {
            a0 = fmaf(k[p], w1[p + 0], a0);
            a1 = fmaf(k[p], w1[p + 1], a1);
            a2 = fmaf(k[p], w1[p + 2], a2);
            a3 = fmaf(k[p], w1[p + 3], a3);
        }
        __stcs(reinterpret_cast<float4*>(orow + d1), make_float4(a0, a1, a2, a3));
    }
}

// ---------------------------------------------------------------------------
// Launch: maxit -> compose2 (PDL) -> conv (PDL). compose2's DRAM prologue
// overlaps maxit; conv's x-load prologue overlaps compose2.
// ---------------------------------------------------------------------------
extern "C" void kernel_launch(void* const* d_in, const int* in_sizes, int n_in,
                              void* d_out, int out_size)
{
    const float* x       = (const float*)d_in[0];   // [4096, 8192] f32
    const int*   g       = (const int*)  d_in[1];   // [4096] i32
    const float* kernels = (const float*)d_in[2];   // [81, 5] f32
    float*       out     = (float*)d_out;           // [4096, 1, 8192] f32

    maxit_kernel<<<1, NTHR>>>(g);

    cudaLaunchAttribute attrs[1];
    attrs[0].id = cudaLaunchAttributeProgrammaticStreamSerialization;
    attrs[0].val.programmaticStreamSerializationAllowed = 1;

    {
        cudaLaunchConfig_t cfg = {};
        cfg.gridDim  = dim3(CBLK, 1, 1);
        cfg.blockDim = dim3(CNTHR, 1, 1);
        cfg.dynamicSmemBytes = 0;
        cfg.stream = 0;
        cfg.attrs = attrs;
        cfg.numAttrs = 1;
        cudaLaunchKernelEx(&cfg, compose2, g, kernels);
    }
    {
        cudaLaunchConfig_t cfg = {};
        cfg.gridDim  = dim3(BB * TILES_PER_ROW, 1, 1);
        cfg.blockDim = dim3(NTHR, 1, 1);
        cfg.dynamicSmemBytes = 0;
        cfg.stream = 0;
        cfg.attrs = attrs;
        cfg.numAttrs = 1;
        cudaLaunchKernelEx(&cfg, conv_main, x, out);
    }
}